// round 10
// baseline (speedup 1.0000x reference)
#include <cuda_runtime.h>

// Inverse 2x2 Haar wavelet — FINAL (converged, 4 consistent runs at
// 43.7-43.9us wall / ~36us kernel, ~6.0 TB/s DRAM = 76% of 8 TB/s spec).
//
// Input  x: [4B, C, H, W] fp32, quadrants k=0..3 at offset k*B*C*H*W
// Output  : [B, C, 2H, 2W] fp32
//
// Work item = (plane, i, j2): 2 consecutive input cols of one input row.
//   loads : 4 x LDG.64  (float2 per quadrant)      -- 256B/warp, fully coalesced
//   stores: 2 x STG.128 (one float4 per output row) -- 512B/warp, fully contiguous
//
// Session ledger (all falsified; do not revisit):
//   R1 baseline float4-loads/half-width-stores: 42.3us kernel, DRAM 64%
//   R2 8-wide per-thread (regs 44, occ 48%):    REGRESSED
//   R3 symmetric .cs hints:                      NEUTRAL
//   R4 lane-contiguous stores (this mapping):    WIN -> 35.8us, DRAM 76%
//   R5 2x MLP at same occupancy:                 NEUTRAL
//   R6 persistent grid-stride:                   REGRESSED (issue serialization)
//   R7 block 512:                                NEUTRAL
//   R8 store-only .cs (evict dead output lines): NEUTRAL (DRAM traffic unchanged)
//   Cross-replay L2 reuse is order-invariant (each line touched once per
//   replay -> constant 268MB reuse gap vs 126MB L2); not improvable in-kernel.

static constexpr int H = 128;
static constexpr int W = 128;
static constexpr int W2 = W / 2;              // 64 j-pairs per input row
static constexpr long long PLANE_IN  = (long long)H * W;         // 16384
static constexpr long long PLANE_OUT = (long long)(2*H) * (2*W); // 65536

__global__ __launch_bounds__(256)
void iwt_kernel(const float* __restrict__ x, float* __restrict__ out,
                long long quad_stride,   // B*C*H*W elements between quadrants
                int n_threads)           // planes * H * W2
{
    int tid = blockIdx.x * blockDim.x + threadIdx.x;
    if (tid >= n_threads) return;

    // tid -> (plane, i, j2)
    int j2    = tid & (W2 - 1);          // 0..63
    int rest  = tid >> 6;
    int i     = rest & (H - 1);          // 0..127
    int plane = rest >> 7;

    long long in_off = (long long)plane * PLANE_IN + (long long)i * W + (long long)j2 * 2;

    const float2 a = __ldg((const float2*)(x + in_off));                    // x1
    const float2 b = __ldg((const float2*)(x + in_off + quad_stride));      // x2
    const float2 c = __ldg((const float2*)(x + in_off + 2 * quad_stride));  // x3
    const float2 d = __ldg((const float2*)(x + in_off + 3 * quad_stride));  // x4

    // butterfly, scaled by 0.5
    float s_ad0 = a.x + d.x, d_ad0 = a.x - d.x;
    float s_bc0 = b.x + c.x, d_bc0 = b.x - c.x;
    float s_ad1 = a.y + d.y, d_ad1 = a.y - d.y;
    float s_bc1 = b.y + c.y, d_bc1 = b.y - c.y;

    float4 r0 = make_float4(0.5f * (s_ad0 - s_bc0), 0.5f * (d_ad0 + d_bc0),
                            0.5f * (s_ad1 - s_bc1), 0.5f * (d_ad1 + d_bc1));
    float4 r1 = make_float4(0.5f * (d_ad0 - d_bc0), 0.5f * (s_ad0 + s_bc0),
                            0.5f * (d_ad1 - d_bc1), 0.5f * (s_ad1 + s_bc1));

    // output rows 2i and 2i+1, cols 4*j2 .. 4*j2+3 (one float4 each)
    long long out_base = (long long)plane * PLANE_OUT
                       + (long long)(2 * i) * (2 * W)
                       + (long long)j2 * 4;

    *(float4*)(out + out_base)         = r0;
    *(float4*)(out + out_base + 2*W)   = r1;
}

extern "C" void kernel_launch(void* const* d_in, const int* in_sizes, int n_in,
                              void* d_out, int out_size) {
    const float* x = (const float*)d_in[0];
    float* out = (float*)d_out;

    long long total = (long long)in_sizes[0];
    long long quad_stride = total / 4;          // B*C*H*W
    long long planes = quad_stride / PLANE_IN;  // B*C
    int n_threads = (int)(planes * H * W2);

    int block = 256;
    int grid = (n_threads + block - 1) / block;
    iwt_kernel<<<grid, block>>>(x, out, quad_stride, n_threads);
}

// round 11
// speedup vs baseline: 1.0044x; 1.0044x over previous
#include <cuda_runtime.h>

// Inverse 2x2 Haar wavelet — FINAL, CONVERGED.
// Five consecutive runs: 35.5-36.4us kernel / 43.7-44.0us wall,
// ~6.0 TB/s DRAM (76% of 8 TB/s spec) — the HBM roofline for this op.
//
// Input  x: [4B, C, H, W] fp32, quadrants k=0..3 at offset k*B*C*H*W
// Output  : [B, C, 2H, 2W] fp32
//
// Work item = (plane, i, j2): 2 consecutive input cols of one input row.
//   loads : 4 x LDG.64  (float2 per quadrant)      -- 256B/warp, fully coalesced
//   stores: 2 x STG.128 (one float4 per output row) -- 512B/warp, fully contiguous
//
// Session ledger (do not revisit):
//   R1 half-width stores baseline:               42.3us kernel, DRAM 64%
//   R2 8-wide per-thread (regs 44, occ 48%):     REGRESSED
//   R3 symmetric .cs hints:                      NEUTRAL
//   R4 lane-contiguous stores (this mapping):    WIN -> ~35.8us, DRAM 76%
//   R5 2x MLP at same occupancy:                 NEUTRAL
//   R6 persistent grid-stride:                   REGRESSED (issue serialization)
//   R7 block 512:                                NEUTRAL
//   R8 store-only .cs:                           NEUTRAL (DRAM traffic unchanged)
//   R9/R10 replication:                          plateau confirmed (noise band)
//   Cross-replay L2 reuse is order-invariant (each line touched once per
//   replay -> constant 268MB reuse gap vs 126MB L2); TMA shares the same
//   LTS throughput cap (path-independent); neither is a lever here.

static constexpr int H = 128;
static constexpr int W = 128;
static constexpr int W2 = W / 2;              // 64 j-pairs per input row
static constexpr long long PLANE_IN  = (long long)H * W;         // 16384
static constexpr long long PLANE_OUT = (long long)(2*H) * (2*W); // 65536

__global__ __launch_bounds__(256)
void iwt_kernel(const float* __restrict__ x, float* __restrict__ out,
                long long quad_stride,   // B*C*H*W elements between quadrants
                int n_threads)           // planes * H * W2
{
    int tid = blockIdx.x * blockDim.x + threadIdx.x;
    if (tid >= n_threads) return;

    // tid -> (plane, i, j2)
    int j2    = tid & (W2 - 1);          // 0..63
    int rest  = tid >> 6;
    int i     = rest & (H - 1);          // 0..127
    int plane = rest >> 7;

    long long in_off = (long long)plane * PLANE_IN + (long long)i * W + (long long)j2 * 2;

    const float2 a = __ldg((const float2*)(x + in_off));                    // x1
    const float2 b = __ldg((const float2*)(x + in_off + quad_stride));      // x2
    const float2 c = __ldg((const float2*)(x + in_off + 2 * quad_stride));  // x3
    const float2 d = __ldg((const float2*)(x + in_off + 3 * quad_stride));  // x4

    // butterfly, scaled by 0.5
    float s_ad0 = a.x + d.x, d_ad0 = a.x - d.x;
    float s_bc0 = b.x + c.x, d_bc0 = b.x - c.x;
    float s_ad1 = a.y + d.y, d_ad1 = a.y - d.y;
    float s_bc1 = b.y + c.y, d_bc1 = b.y - c.y;

    float4 r0 = make_float4(0.5f * (s_ad0 - s_bc0), 0.5f * (d_ad0 + d_bc0),
                            0.5f * (s_ad1 - s_bc1), 0.5f * (d_ad1 + d_bc1));
    float4 r1 = make_float4(0.5f * (d_ad0 - d_bc0), 0.5f * (s_ad0 + s_bc0),
                            0.5f * (d_ad1 - d_bc1), 0.5f * (s_ad1 + s_bc1));

    // output rows 2i and 2i+1, cols 4*j2 .. 4*j2+3 (one float4 each)
    long long out_base = (long long)plane * PLANE_OUT
                       + (long long)(2 * i) * (2 * W)
                       + (long long)j2 * 4;

    *(float4*)(out + out_base)         = r0;
    *(float4*)(out + out_base + 2*W)   = r1;
}

extern "C" void kernel_launch(void* const* d_in, const int* in_sizes, int n_in,
                              void* d_out, int out_size) {
    const float* x = (const float*)d_in[0];
    float* out = (float*)d_out;

    long long total = (long long)in_sizes[0];
    long long quad_stride = total / 4;          // B*C*H*W
    long long planes = quad_stride / PLANE_IN;  // B*C
    int n_threads = (int)(planes * H * W2);

    int block = 256;
    int grid = (n_threads + block - 1) / block;
    iwt_kernel<<<grid, block>>>(x, out, quad_stride, n_threads);
}